// round 1
// baseline (speedup 1.0000x reference)
#include <cuda_runtime.h>
#include <math.h>

// Problem constants
#define BT        3136     // B*T tokens
#define NJ        43       // joints
#define NJ6       13       // joints with 6-dim output
#define DLAT      512      // latent dim
#define OUTCOLS   168      // 13*6 + 30*3

// Tiling
#define TM        64       // tokens per CTA
#define TN        64       // N-chunk of GEMM1
#define KB        32       // K-chunk streamed through smem
#define NTHREADS  256
#define XS_STRIDE 516      // padded row stride for x tile (floats), 16B-aligned, bank-skewed
#define HS_STRIDE 68       // padded row stride for h tile (floats), 16B-aligned

// Dynamic smem layout (in floats):
//   xs  [TM][XS_STRIDE]   = 33024 floats  (x tile, token-major)
//   ws  [KB][TN]          =  2048 floats  (W1 K-chunk)
//   hs  [TM][HS_STRIDE]   =  4352 floats  (gelu'd h chunk)
//   w2s [DLAT*odim<=6]    =  3072 floats  (full W2 for this joint)
#define XS_OFF   0
#define WS_OFF   33024
#define HS_OFF   35072
#define W2S_OFF  39424
#define SMEM_FLOATS 42496
#define SMEM_BYTES  (SMEM_FLOATS * 4)

__device__ __forceinline__ float gelu_erf(float v) {
    return 0.5f * v * (1.0f + erff(v * 0.70710678118654752f));
}

__global__ __launch_bounds__(NTHREADS, 1)
void motion_decoder_kernel(const float* __restrict__ x,
                           const float* __restrict__ W1,
                           const float* __restrict__ b1,
                           const float* __restrict__ W2a,
                           const float* __restrict__ b2a,
                           const float* __restrict__ W2b,
                           const float* __restrict__ b2b,
                           float* __restrict__ out)
{
    extern __shared__ float sm[];
    float* xs  = sm + XS_OFF;
    float* ws  = sm + WS_OFF;
    float* hs  = sm + HS_OFF;
    float* w2s = sm + W2S_OFF;

    const int j    = blockIdx.y;          // joint
    const int tok0 = blockIdx.x * TM;     // first token of this CTA
    const int tid  = threadIdx.x;

    const int odim = (j < NJ6) ? 6 : 3;
    const float* W2 = (j < NJ6) ? (W2a + (size_t)j * DLAT * 6)
                                : (W2b + (size_t)(j - NJ6) * DLAT * 3);
    const float* b2 = (j < NJ6) ? (b2a + j * 6) : (b2b + (j - NJ6) * 3);
    const int colbase = (j < NJ6) ? j * 6 : (NJ6 * 6 + (j - NJ6) * 3);

    // ---- Load x tile [TM][DLAT] into smem (token-major, padded) ----
    // 64 tokens * 128 float4 = 8192 float4 -> 32 per thread, fully coalesced.
    for (int i = tid; i < TM * (DLAT / 4); i += NTHREADS) {
        const int m  = i >> 7;            // / 128
        const int k4 = i & 127;
        const float4 v = ((const float4*)(x + ((size_t)(tok0 + m) * NJ + j) * DLAT))[k4];
        *(float4*)(xs + m * XS_STRIDE + k4 * 4) = v;
    }
    // ---- Load W2[j] fully into smem ----
    for (int i = tid; i < DLAT * odim; i += NTHREADS) w2s[i] = W2[i];

    const int ty = tid >> 4;   // 0..15  -> token micro-rows ty*4..ty*4+3
    const int tx = tid & 15;   // 0..15  -> n micro-cols   tx*4..tx*4+3

    // Output accumulators for GEMM2: up to 2 (token,o) pairs per thread (64*6=384).
    float oacc0 = 0.f, oacc1 = 0.f;

    const float* W1jbase = W1 + (size_t)j * DLAT * DLAT;

    #pragma unroll 1
    for (int nc = 0; nc < DLAT / TN; ++nc) {   // 8 N-chunks
        const int n0 = nc * TN;

        // init GEMM1 accumulators with b1
        float acc[4][4];
        #pragma unroll
        for (int c = 0; c < 4; ++c) {
            const float bv = b1[j * DLAT + n0 + tx * 4 + c];
            #pragma unroll
            for (int i = 0; i < 4; ++i) acc[i][c] = bv;
        }

        const float* W1j = W1jbase + n0;

        #pragma unroll 1
        for (int kb = 0; kb < DLAT; kb += KB) {
            __syncthreads();
            // Load ws[KB][TN]: 512 float4, 2 per thread, coalesced 256B rows.
            #pragma unroll
            for (int r = 0; r < 2; ++r) {
                const int idx = tid + r * NTHREADS;     // float4 index
                const int k   = idx >> 4;
                const int nn  = (idx & 15) * 4;
                *(float4*)(ws + k * TN + nn) =
                    *(const float4*)(W1j + (size_t)(kb + k) * DLAT + nn);
            }
            __syncthreads();

            #pragma unroll
            for (int k4 = 0; k4 < KB; k4 += 4) {
                float av[4][4], bv[4][4];
                #pragma unroll
                for (int i = 0; i < 4; ++i) {
                    const float4 t = *(const float4*)(xs + (ty * 4 + i) * XS_STRIDE + kb + k4);
                    av[i][0] = t.x; av[i][1] = t.y; av[i][2] = t.z; av[i][3] = t.w;
                }
                #pragma unroll
                for (int kk = 0; kk < 4; ++kk) {
                    const float4 t = *(const float4*)(ws + (k4 + kk) * TN + tx * 4);
                    bv[kk][0] = t.x; bv[kk][1] = t.y; bv[kk][2] = t.z; bv[kk][3] = t.w;
                }
                #pragma unroll
                for (int kk = 0; kk < 4; ++kk)
                    #pragma unroll
                    for (int i = 0; i < 4; ++i)
                        #pragma unroll
                        for (int c = 0; c < 4; ++c)
                            acc[i][c] += av[i][kk] * bv[kk][c];
            }
        }

        // GELU (exact erf) + store h chunk to smem
        #pragma unroll
        for (int i = 0; i < 4; ++i) {
            float4 hv;
            hv.x = gelu_erf(acc[i][0]);
            hv.y = gelu_erf(acc[i][1]);
            hv.z = gelu_erf(acc[i][2]);
            hv.w = gelu_erf(acc[i][3]);
            *(float4*)(hs + (ty * 4 + i) * HS_STRIDE + tx * 4) = hv;
        }
        __syncthreads();

        // GEMM2 partial: out_acc[token][o] += h_chunk[token][:] @ w2s[n0: n0+TN][o]
        {
            int slot = 0;
            for (int idx = tid; idx < TM * odim; idx += NTHREADS, ++slot) {
                const int token = idx / odim;
                const int o     = idx - token * odim;
                float s = 0.f;
                const float* hrow = hs + token * HS_STRIDE;
                const float* wcol = w2s + n0 * odim + o;
                #pragma unroll 8
                for (int kk = 0; kk < TN; ++kk)
                    s += hrow[kk] * wcol[kk * odim];
                if (slot == 0) oacc0 += s; else oacc1 += s;
            }
        }
        // next iteration's leading __syncthreads() protects hs reuse
    }

    // ---- Final write: each (token, col) written by exactly one thread ----
    {
        int slot = 0;
        for (int idx = tid; idx < TM * odim; idx += NTHREADS, ++slot) {
            const int token = idx / odim;
            const int o     = idx - token * odim;
            const float v   = ((slot == 0) ? oacc0 : oacc1) + b2[o];
            out[(size_t)(tok0 + token) * OUTCOLS + colbase + o] = v;
        }
    }
}

extern "C" void kernel_launch(void* const* d_in, const int* in_sizes, int n_in,
                              void* d_out, int out_size)
{
    const float* x   = (const float*)d_in[0];
    const float* W1  = (const float*)d_in[1];
    const float* b1  = (const float*)d_in[2];
    const float* W2a = (const float*)d_in[3];
    const float* b2a = (const float*)d_in[4];
    const float* W2b = (const float*)d_in[5];
    const float* b2b = (const float*)d_in[6];
    float* out = (float*)d_out;

    cudaFuncSetAttribute(motion_decoder_kernel,
                         cudaFuncAttributeMaxDynamicSharedMemorySize, SMEM_BYTES);

    dim3 grid(BT / TM, NJ);   // 49 x 43; token-block fastest -> same-joint CTAs co-resident (L2 W1 reuse)
    motion_decoder_kernel<<<grid, NTHREADS, SMEM_BYTES>>>(x, W1, b1, W2a, b2a, W2b, b2b, out);
}

// round 5
// speedup vs baseline: 2.7412x; 2.7412x over previous
#include <cuda_runtime.h>
#include <cuda_bf16.h>
#include <math.h>
#include <stdint.h>

// ---------------- problem constants ----------------
#define BT      3136
#define NJ      43
#define NJ6     13
#define DLAT    512
#define OUTC    168

// ---------------- tiling ----------------
#define TM       128      // tokens per CTA
#define NCHUNK   128      // N per chunk (4 chunks)
#define KCH      64       // K per chunk (8 chunks)
#define NTHREADS 256      // 8 warps: 2 (m) x 4 (n)

// ---------------- smem layout (bytes) ----------------
// A: [hi/lo][128][64] bf16, 128B rows, swizzled           -> 32768
// B: [hi/lo][64][128] bf16, 256B rows, swizzled           -> 32768
// H: [128][132] fp32                                      -> 67584
// b1s: 512 fp32                                           -> 2048
// w2t: [6][516] fp32 (transposed W2, padded)              -> 12384
#define OFF_A    0
#define OFF_B    32768
#define OFF_H    65536
#define OFF_B1   133120
#define OFF_W2T  135168
#define SMEM_BYTES 147584

#define ASWZ(x) ((x) ^ (((x) >> 3) & 0x70))   // 128B rows: bits[6:4] ^= row&7
#define BSWZ(x) ((x) ^ (((x) >> 4) & 0x70))   // 256B rows: bits[6:4] ^= row&7
#define HSTR 132
#define W2STR 516

__device__ __forceinline__ uint32_t smem_u32(const void* p) {
    uint32_t a;
    asm("{ .reg .u64 t; cvta.to.shared.u64 t, %1; cvt.u32.u64 %0, t; }" : "=r"(a) : "l"(p));
    return a;
}

__device__ __forceinline__ float gelu_erf(float v) {
    return 0.5f * v * (1.0f + erff(v * 0.70710678118654752f));
}

// ---------------- bf16 split helpers ----------------
__device__ __forceinline__ uint32_t pk(__nv_bfloat16 a, __nv_bfloat16 b) {
    return (uint32_t)__bfloat16_as_ushort(a) | ((uint32_t)__bfloat16_as_ushort(b) << 16);
}
__device__ __forceinline__ void split4(float4 v, uint2* h, uint2* l) {
    __nv_bfloat16 bx = __float2bfloat16(v.x), by = __float2bfloat16(v.y);
    __nv_bfloat16 bz = __float2bfloat16(v.z), bw = __float2bfloat16(v.w);
    h->x = pk(bx, by); h->y = pk(bz, bw);
    __nv_bfloat16 lx = __float2bfloat16(v.x - __bfloat162float(bx));
    __nv_bfloat16 ly = __float2bfloat16(v.y - __bfloat162float(by));
    __nv_bfloat16 lz = __float2bfloat16(v.z - __bfloat162float(bz));
    __nv_bfloat16 lw = __float2bfloat16(v.w - __bfloat162float(bw));
    l->x = pk(lx, ly); l->y = pk(lz, lw);
}

// ---------------- mma / ldmatrix ----------------
__device__ __forceinline__ void ldsm4(uint32_t* r, uint32_t addr) {
    asm volatile("ldmatrix.sync.aligned.m8n8.x4.shared.b16 {%0,%1,%2,%3}, [%4];"
                 : "=r"(r[0]), "=r"(r[1]), "=r"(r[2]), "=r"(r[3]) : "r"(addr));
}
__device__ __forceinline__ void ldsm4t(uint32_t* r, uint32_t addr) {
    asm volatile("ldmatrix.sync.aligned.m8n8.x4.trans.shared.b16 {%0,%1,%2,%3}, [%4];"
                 : "=r"(r[0]), "=r"(r[1]), "=r"(r[2]), "=r"(r[3]) : "r"(addr));
}
__device__ __forceinline__ void mma16816(float* c, const uint32_t* a, const uint32_t* b) {
    asm volatile("mma.sync.aligned.m16n8k16.row.col.f32.bf16.bf16.f32 "
                 "{%0,%1,%2,%3}, {%4,%5,%6,%7}, {%8,%9}, {%0,%1,%2,%3};"
                 : "+f"(c[0]), "+f"(c[1]), "+f"(c[2]), "+f"(c[3])
                 : "r"(a[0]), "r"(a[1]), "r"(a[2]), "r"(a[3]), "r"(b[0]), "r"(b[1]));
}

// ---------------- tile loaders (fp32 gmem -> split bf16 smem) ----------------
__device__ __forceinline__ void load_a(char* sm, const float* __restrict__ x,
                                       int j, int tok0, int kc, int tid) {
    char* hi = sm + OFF_A;
    char* lo = sm + OFF_A + 16384;
    #pragma unroll
    for (int r = 0; r < 8; ++r) {
        int idx = tid + r * NTHREADS;      // 0..2047
        int m = idx >> 4, k4 = idx & 15;
        int token = tok0 + m;
        float4 v = make_float4(0.f, 0.f, 0.f, 0.f);
        if (token < BT)
            v = *(const float4*)(x + ((size_t)token * NJ + j) * DLAT + kc * KCH + k4 * 4);
        uint2 h, l; split4(v, &h, &l);
        uint32_t o = ASWZ((uint32_t)(m * 128 + k4 * 8));
        *(uint2*)(hi + o) = h;
        *(uint2*)(lo + o) = l;
    }
}

__device__ __forceinline__ void load_b(char* sm, const float* __restrict__ W1,
                                       int j, int kc, int nc, int tid) {
    char* hi = sm + OFF_B;
    char* lo = sm + OFF_B + 16384;
    const float* wp = W1 + (size_t)j * DLAT * DLAT + (size_t)(kc * KCH) * DLAT + nc * NCHUNK;
    #pragma unroll
    for (int r = 0; r < 8; ++r) {
        int idx = tid + r * NTHREADS;      // 0..2047
        int k = idx >> 5, n4 = idx & 31;
        float4 v = *(const float4*)(wp + (size_t)k * DLAT + n4 * 4);
        uint2 h, l; split4(v, &h, &l);
        uint32_t o = BSWZ((uint32_t)(k * 256 + n4 * 8));
        *(uint2*)(hi + o) = h;
        *(uint2*)(lo + o) = l;
    }
}

// ---------------- kernel ----------------
__global__ __launch_bounds__(NTHREADS, 1)
void motion_decoder_mma(const float* __restrict__ x,
                        const float* __restrict__ W1,
                        const float* __restrict__ b1,
                        const float* __restrict__ W2a,
                        const float* __restrict__ b2a,
                        const float* __restrict__ W2b,
                        const float* __restrict__ b2b,
                        float* __restrict__ out)
{
    extern __shared__ char sm[];
    const uint32_t smb = smem_u32(sm);
    const int tid = threadIdx.x;
    const int wid = tid >> 5, lane = tid & 31;
    const int wm = wid >> 2;               // 0..1 -> m offset wm*64
    const int wn = wid & 3;                // 0..3 -> n offset wn*32
    const int j = blockIdx.y;
    const int tok0 = blockIdx.x * TM;

    const int odim = (j < NJ6) ? 6 : 3;
    const float* W2 = (j < NJ6) ? (W2a + (size_t)j * DLAT * 6)
                                : (W2b + (size_t)(j - NJ6) * DLAT * 3);
    const float* b2 = (j < NJ6) ? (b2a + j * 6) : (b2b + (j - NJ6) * 3);
    const int colbase = (j < NJ6) ? j * 6 : (NJ6 * 6 + (j - NJ6) * 3);

    // preload b1 and W2 (transposed, padded) into smem
    float* b1s = (float*)(sm + OFF_B1);
    for (int i = tid; i < DLAT; i += NTHREADS) b1s[i] = b1[j * DLAT + i];
    float* w2t = (float*)(sm + OFF_W2T);
    for (int i = tid; i < DLAT * odim; i += NTHREADS) {
        int o = i / DLAT, n = i - o * DLAT;
        w2t[o * W2STR + n] = W2[n * odim + o];
    }

    float* hsm = (float*)(sm + OFF_H);

    const int l15 = lane & 15;
    const int lhi = lane >> 4;             // 0/1

    float oacc[3] = {0.f, 0.f, 0.f};

    #pragma unroll 1
    for (int nc = 0; nc < 4; ++nc) {
        float c[4][4][4];                  // [mt][nt][frag]
        #pragma unroll
        for (int mt = 0; mt < 4; ++mt)
            #pragma unroll
            for (int nt = 0; nt < 4; ++nt)
                #pragma unroll
                for (int q = 0; q < 4; ++q) c[mt][nt][q] = 0.f;

        #pragma unroll 1
        for (int kc = 0; kc < 8; ++kc) {
            __syncthreads();               // prior mma/GEMM2 consumers done
            load_a(sm, x, j, tok0, kc, tid);
            load_b(sm, W1, j, kc, nc, tid);
            __syncthreads();

            #pragma unroll
            for (int kt = 0; kt < 4; ++kt) {
                // --- A hi fragments (4 m-tiles) ---
                uint32_t ah[4][4];
                #pragma unroll
                for (int mt = 0; mt < 4; ++mt) {
                    int row = wm * 64 + mt * 16 + l15;
                    uint32_t off = ASWZ((uint32_t)(row * 128 + kt * 32 + lhi * 16));
                    ldsm4(ah[mt], smb + OFF_A + off);
                }
                // --- B hi fragments (2x n16) ---
                uint32_t bh[2][4];
                #pragma unroll
                for (int nt2 = 0; nt2 < 2; ++nt2) {
                    int krow = kt * 16 + l15;
                    uint32_t off = BSWZ((uint32_t)(krow * 256 + wn * 64 + nt2 * 32 + lhi * 16));
                    ldsm4t(bh[nt2], smb + OFF_B + off);
                }
                // hi * hi
                #pragma unroll
                for (int mt = 0; mt < 4; ++mt)
                    #pragma unroll
                    for (int nt = 0; nt < 4; ++nt)
                        mma16816(c[mt][nt], ah[mt], &bh[nt >> 1][(nt & 1) * 2]);
                // --- B lo, hi * lo ---
                uint32_t bl[2][4];
                #pragma unroll
                for (int nt2 = 0; nt2 < 2; ++nt2) {
                    int krow = kt * 16 + l15;
                    uint32_t off = BSWZ((uint32_t)(krow * 256 + wn * 64 + nt2 * 32 + lhi * 16));
                    ldsm4t(bl[nt2], smb + OFF_B + 16384 + off);
                }
                #pragma unroll
                for (int mt = 0; mt < 4; ++mt)
                    #pragma unroll
                    for (int nt = 0; nt < 4; ++nt)
                        mma16816(c[mt][nt], ah[mt], &bl[nt >> 1][(nt & 1) * 2]);
                // --- A lo, lo * hi ---
                uint32_t al[4];
                #pragma unroll
                for (int mt = 0; mt < 4; ++mt) {
                    int row = wm * 64 + mt * 16 + l15;
                    uint32_t off = ASWZ((uint32_t)(row * 128 + kt * 32 + lhi * 16));
                    ldsm4(al, smb + OFF_A + 16384 + off);
                    #pragma unroll
                    for (int nt = 0; nt < 4; ++nt)
                        mma16816(c[mt][nt], al, &bh[nt >> 1][(nt & 1) * 2]);
                }
            }
        }

        // ---- epilogue for this N-chunk: bias + GELU -> h smem ----
        {
            const int r0 = wm * 64 + (lane >> 2);
            #pragma unroll
            for (int mt = 0; mt < 4; ++mt) {
                #pragma unroll
                for (int nt = 0; nt < 4; ++nt) {
                    const int ncol = wn * 32 + nt * 8 + (lane & 3) * 2;
                    const int ng = nc * NCHUNK + ncol;
                    const float bv0 = b1s[ng], bv1 = b1s[ng + 1];
                    float2 v0, v1;
                    v0.x = gelu_erf(c[mt][nt][0] + bv0);
                    v0.y = gelu_erf(c[mt][nt][1] + bv1);
                    v1.x = gelu_erf(c[mt][nt][2] + bv0);
                    v1.y = gelu_erf(c[mt][nt][3] + bv1);
                    *(float2*)(hsm + (r0 + mt * 16) * HSTR + ncol) = v0;
                    *(float2*)(hsm + (r0 + mt * 16 + 8) * HSTR + ncol) = v1;
                }
            }
        }
        __syncthreads();

        // ---- GEMM2 partial over this chunk's 128 n ----
        #pragma unroll
        for (int p = 0; p < 3; ++p) {
            const int idx = tid + p * NTHREADS;
            if (idx < TM * odim) {
                const int m = idx / odim;
                const int o = idx - m * odim;
                const float* hrow = hsm + m * HSTR;
                const float* wrow = w2t + o * W2STR + nc * NCHUNK;
                float s = 0.f;
                #pragma unroll 8
                for (int n4 = 0; n4 < NCHUNK / 4; ++n4) {
                    const float4 hv = *(const float4*)(hrow + n4 * 4);
                    const float4 wv = *(const float4*)(wrow + n4 * 4);
                    s += hv.x * wv.x + hv.y * wv.y + hv.z * wv.z + hv.w * wv.w;
                }
                oacc[p] += s;
            }
        }
    }

    // ---- final write ----
    #pragma unroll
    for (int p = 0; p < 3; ++p) {
        const int idx = tid + p * NTHREADS;
        if (idx < TM * odim) {
            const int m = idx / odim;
            const int o = idx - m * odim;
            const int token = tok0 + m;
            if (token < BT)
                out[(size_t)token * OUTC + colbase + o] = oacc[p] + b2[o];
        }
    }
}

extern "C" void kernel_launch(void* const* d_in, const int* in_sizes, int n_in,
                              void* d_out, int out_size)
{
    const float* x   = (const float*)d_in[0];
    const float* W1  = (const float*)d_in[1];
    const float* b1  = (const float*)d_in[2];
    const float* W2a = (const float*)d_in[3];
    const float* b2a = (const float*)d_in[4];
    const float* W2b = (const float*)d_in[5];
    const float* b2b = (const float*)d_in[6];
    float* out = (float*)d_out;

    cudaFuncSetAttribute(motion_decoder_mma,
                         cudaFuncAttributeMaxDynamicSharedMemorySize, SMEM_BYTES);

    dim3 grid((BT + TM - 1) / TM, NJ);   // 25 x 43
    motion_decoder_mma<<<grid, NTHREADS, SMEM_BYTES>>>(x, W1, b1, W2a, b2a, W2b, b2b, out);
}

// round 6
// speedup vs baseline: 3.3361x; 1.2170x over previous
#include <cuda_runtime.h>
#include <cuda_bf16.h>
#include <math.h>
#include <stdint.h>

// ---------------- problem constants ----------------
#define BT      3136
#define NJ      43
#define NJ6     13
#define DLAT    512
#define OUTC    168

// ---------------- tiling ----------------
#define TM       128      // tokens per CTA
#define NCHUNK   128      // N per chunk (4 chunks)
#define KCH      64       // K per chunk (8 chunks)
#define NTHREADS 512      // 16 warps: 4 (m) x 4 (n), warp tile m32 n32

// ---------------- smem layout (bytes) ----------------
#define OFF_ARAW 0                         // fp32 A stage [128][64]      32768
#define OFF_AH   32768                     // bf16 A hi [128][64]         16384
#define OFF_AL   49152                     // bf16 A lo                   16384
#define OFF_B    65536                     // 2 x (hi 16K + lo 16K)       65536
#define B_HI(b)  (OFF_B + (b)*32768)
#define B_LO(b)  (OFF_B + (b)*32768 + 16384)
#define OFF_H    131072                    // fp32 H [128][132]           67584
#define OFF_B1   198656                    // 512 fp32                     2048
#define OFF_W2T  200704                    // [6][516] fp32               12384
#define SMEM_BYTES 213088

#define ASWZ(x) ((x) ^ (((x) >> 3) & 0x70))   // 128B rows
#define BSWZ(x) ((x) ^ (((x) >> 4) & 0x70))   // 256B rows
#define HSTR 132
#define W2STR 516

// ---------------- device scratch: preconverted W1 (bf16 hi/lo) ----------------
__device__ __nv_bfloat16 g_w1hi[(size_t)NJ * DLAT * DLAT];
__device__ __nv_bfloat16 g_w1lo[(size_t)NJ * DLAT * DLAT];

__device__ __forceinline__ uint32_t smem_u32(const void* p) {
    uint32_t a;
    asm("{ .reg .u64 t; cvta.to.shared.u64 t, %1; cvt.u32.u64 %0, t; }" : "=r"(a) : "l"(p));
    return a;
}

__device__ __forceinline__ float gelu_erf(float v) {
    return 0.5f * v * (1.0f + erff(v * 0.70710678118654752f));
}

// ---------------- bf16 split helpers ----------------
__device__ __forceinline__ uint32_t pk(__nv_bfloat16 a, __nv_bfloat16 b) {
    return (uint32_t)__bfloat16_as_ushort(a) | ((uint32_t)__bfloat16_as_ushort(b) << 16);
}
__device__ __forceinline__ void split4(float4 v, uint2* h, uint2* l) {
    __nv_bfloat16 bx = __float2bfloat16(v.x), by = __float2bfloat16(v.y);
    __nv_bfloat16 bz = __float2bfloat16(v.z), bw = __float2bfloat16(v.w);
    h->x = pk(bx, by); h->y = pk(bz, bw);
    __nv_bfloat16 lx = __float2bfloat16(v.x - __bfloat162float(bx));
    __nv_bfloat16 ly = __float2bfloat16(v.y - __bfloat162float(by));
    __nv_bfloat16 lz = __float2bfloat16(v.z - __bfloat162float(bz));
    __nv_bfloat16 lw = __float2bfloat16(v.w - __bfloat162float(bw));
    l->x = pk(lx, ly); l->y = pk(lz, lw);
}

// ---------------- cp.async ----------------
__device__ __forceinline__ void cpa16(uint32_t dst, const void* src, int ssz) {
    asm volatile("cp.async.cg.shared.global [%0], [%1], 16, %2;"
                 :: "r"(dst), "l"(src), "r"(ssz) : "memory");
}
#define CP_COMMIT() asm volatile("cp.async.commit_group;" ::: "memory")
#define CP_WAIT0()  asm volatile("cp.async.wait_group 0;" ::: "memory")

// ---------------- mma / ldmatrix ----------------
__device__ __forceinline__ void ldsm4(uint32_t* r, uint32_t addr) {
    asm volatile("ldmatrix.sync.aligned.m8n8.x4.shared.b16 {%0,%1,%2,%3}, [%4];"
                 : "=r"(r[0]), "=r"(r[1]), "=r"(r[2]), "=r"(r[3]) : "r"(addr));
}
__device__ __forceinline__ void ldsm4t(uint32_t* r, uint32_t addr) {
    asm volatile("ldmatrix.sync.aligned.m8n8.x4.trans.shared.b16 {%0,%1,%2,%3}, [%4];"
                 : "=r"(r[0]), "=r"(r[1]), "=r"(r[2]), "=r"(r[3]) : "r"(addr));
}
__device__ __forceinline__ void mma16816(float* c, const uint32_t* a, const uint32_t* b) {
    asm volatile("mma.sync.aligned.m16n8k16.row.col.f32.bf16.bf16.f32 "
                 "{%0,%1,%2,%3}, {%4,%5,%6,%7}, {%8,%9}, {%0,%1,%2,%3};"
                 : "+f"(c[0]), "+f"(c[1]), "+f"(c[2]), "+f"(c[3])
                 : "r"(a[0]), "r"(a[1]), "r"(a[2]), "r"(a[3]), "r"(b[0]), "r"(b[1]));
}

// ---------------- W1 preconvert kernel ----------------
__global__ __launch_bounds__(512, 2)
void convert_w1_kernel(const float* __restrict__ W1) {
    const size_t idx = (size_t)blockIdx.x * 512 + threadIdx.x;   // float4 index, exact fit
    const float4 v = ((const float4*)W1)[idx];
    uint2 h, l; split4(v, &h, &l);
    ((uint2*)g_w1hi)[idx] = h;
    ((uint2*)g_w1lo)[idx] = l;
}

// ---------------- prefetch / convert ----------------
__device__ __forceinline__ void prefetch_a(uint32_t smb, const float* __restrict__ x,
                                           int j, int tok0, int kc, int tid) {
    #pragma unroll
    for (int r = 0; r < 4; ++r) {
        const int idx = tid + r * NTHREADS;     // 0..2047
        const int m = idx >> 4, k4 = idx & 15;
        const int token = tok0 + m;
        const float* src = x + ((size_t)token * NJ + j) * DLAT + kc * KCH + k4 * 4;
        cpa16(smb + OFF_ARAW + idx * 16, src, token < BT ? 16 : 0);
    }
}

__device__ __forceinline__ void prefetch_b(uint32_t smb, int buf, int j, int kc, int nc, int tid) {
    const size_t base = (size_t)j * DLAT * DLAT + (size_t)(kc * KCH) * DLAT + nc * NCHUNK;
    #pragma unroll
    for (int r = 0; r < 2; ++r) {
        const int idx = tid + r * NTHREADS;     // 0..1023
        const int k = idx >> 4, n8 = idx & 15;
        const size_t g = base + (size_t)k * DLAT + n8 * 8;
        const uint32_t o = BSWZ((uint32_t)(k * 256 + n8 * 16));
        cpa16(smb + B_HI(buf) + o, g_w1hi + g, 16);
        cpa16(smb + B_LO(buf) + o, g_w1lo + g, 16);
    }
}

__device__ __forceinline__ void convert_a(char* sm, int tid) {
    #pragma unroll
    for (int r = 0; r < 4; ++r) {
        const int idx = tid + r * NTHREADS;
        const float4 v = *(const float4*)(sm + OFF_ARAW + idx * 16);
        uint2 h, l; split4(v, &h, &l);
        const int m = idx >> 4, k4 = idx & 15;
        const uint32_t o = ASWZ((uint32_t)(m * 128 + k4 * 8));
        *(uint2*)(sm + OFF_AH + o) = h;
        *(uint2*)(sm + OFF_AL + o) = l;
    }
}

// ---------------- main kernel ----------------
__global__ __launch_bounds__(NTHREADS, 1)
void motion_decoder_mma(const float* __restrict__ x,
                        const float* __restrict__ b1,
                        const float* __restrict__ W2a,
                        const float* __restrict__ b2a,
                        const float* __restrict__ W2b,
                        const float* __restrict__ b2b,
                        float* __restrict__ out)
{
    extern __shared__ char sm[];
    const uint32_t smb = smem_u32(sm);
    const int tid = threadIdx.x;
    const int wid = tid >> 5, lane = tid & 31;
    const int wm = wid >> 2;               // 0..3 -> m offset wm*32
    const int wn = wid & 3;                // 0..3 -> n offset wn*32
    const int j = blockIdx.y;
    const int tok0 = blockIdx.x * TM;

    const int odim = (j < NJ6) ? 6 : 3;
    const float* W2 = (j < NJ6) ? (W2a + (size_t)j * DLAT * 6)
                                : (W2b + (size_t)(j - NJ6) * DLAT * 3);
    const float* b2 = (j < NJ6) ? (b2a + j * 6) : (b2b + (j - NJ6) * 3);
    const int colbase = (j < NJ6) ? j * 6 : (NJ6 * 6 + (j - NJ6) * 3);

    // pipeline prologue: stage 0 tiles in flight
    prefetch_a(smb, x, j, tok0, 0, tid);
    prefetch_b(smb, 0, j, 0, 0, tid);
    CP_COMMIT();

    // preload b1 and W2 (transposed, padded)
    float* b1s = (float*)(sm + OFF_B1);
    for (int i = tid; i < DLAT; i += NTHREADS) b1s[i] = b1[j * DLAT + i];
    float* w2t = (float*)(sm + OFF_W2T);
    for (int i = tid; i < DLAT * odim; i += NTHREADS) {
        int o = i / DLAT, n = i - o * DLAT;
        w2t[o * W2STR + n] = W2[n * odim + o];
    }

    float* hsm = (float*)(sm + OFF_H);
    const int l15 = lane & 15;
    const int lhi = lane >> 4;

    float oacc[2] = {0.f, 0.f};

    #pragma unroll 1
    for (int nc = 0; nc < 4; ++nc) {
        float c[2][4][4];                  // [mt][nt][frag], warp tile m32 n32
        #pragma unroll
        for (int mt = 0; mt < 2; ++mt)
            #pragma unroll
            for (int nt = 0; nt < 4; ++nt)
                #pragma unroll
                for (int q = 0; q < 4; ++q) c[mt][nt][q] = 0.f;

        #pragma unroll 1
        for (int kc = 0; kc < 8; ++kc) {
            const int s = nc * 8 + kc;
            CP_WAIT0();                    // A raw(s), B(s) landed
            __syncthreads();               // ...and prior MMA/readers done
            convert_a(sm, tid);            // fp32 smem -> bf16 hi/lo smem
            __syncthreads();               // convert done before overwrite/use

            if (s < 31) {                  // prefetch stage s+1 during MMA(s)
                const int s2 = s + 1;
                prefetch_a(smb, x, j, tok0, s2 & 7, tid);
                prefetch_b(smb, s2 & 1, j, s2 & 7, s2 >> 3, tid);
            }
            CP_COMMIT();

            const int buf = s & 1;
            const uint32_t abh = smb + OFF_AH, abl = smb + OFF_AL;
            const uint32_t bbh = smb + B_HI(buf), bbl = smb + B_LO(buf);

            #pragma unroll
            for (int kt = 0; kt < 4; ++kt) {
                uint32_t ah[2][4], bh[2][4], bl[2][4], al[4];
                #pragma unroll
                for (int mt = 0; mt < 2; ++mt) {
                    const int row = wm * 32 + mt * 16 + l15;
                    ldsm4(ah[mt], abh + ASWZ((uint32_t)(row * 128 + kt * 32 + lhi * 16)));
                }
                #pragma unroll
                for (int nt2 = 0; nt2 < 2; ++nt2) {
                    const int krow = kt * 16 + l15;
                    ldsm4t(bh[nt2], bbh + BSWZ((uint32_t)(krow * 256 + wn * 64 + nt2 * 32 + lhi * 16)));
                }
                // hi * hi
                #pragma unroll
                for (int mt = 0; mt < 2; ++mt)
                    #pragma unroll
                    for (int nt = 0; nt < 4; ++nt)
                        mma16816(c[mt][nt], ah[mt], &bh[nt >> 1][(nt & 1) * 2]);
                // hi * lo
                #pragma unroll
                for (int nt2 = 0; nt2 < 2; ++nt2) {
                    const int krow = kt * 16 + l15;
                    ldsm4t(bl[nt2], bbl + BSWZ((uint32_t)(krow * 256 + wn * 64 + nt2 * 32 + lhi * 16)));
                }
                #pragma unroll
                for (int mt = 0; mt < 2; ++mt)
                    #pragma unroll
                    for (int nt = 0; nt < 4; ++nt)
                        mma16816(c[mt][nt], ah[mt], &bl[nt >> 1][(nt & 1) * 2]);
                // lo * hi
                #pragma unroll
                for (int mt = 0; mt < 2; ++mt) {
                    const int row = wm * 32 + mt * 16 + l15;
                    ldsm4(al, abl + ASWZ((uint32_t)(row * 128 + kt * 32 + lhi * 16)));
                    #pragma unroll
                    for (int nt = 0; nt < 4; ++nt)
                        mma16816(c[mt][nt], al, &bh[nt >> 1][(nt & 1) * 2]);
                }
            }
        }

        // ---- epilogue: bias + GELU -> h smem ----
        {
            const int r0 = wm * 32 + (lane >> 2);
            #pragma unroll
            for (int mt = 0; mt < 2; ++mt) {
                #pragma unroll
                for (int nt = 0; nt < 4; ++nt) {
                    const int ncol = wn * 32 + nt * 8 + (lane & 3) * 2;
                    const int ng = nc * NCHUNK + ncol;
                    const float bv0 = b1s[ng], bv1 = b1s[ng + 1];
                    float2 v0, v1;
                    v0.x = gelu_erf(c[mt][nt][0] + bv0);
                    v0.y = gelu_erf(c[mt][nt][1] + bv1);
                    v1.x = gelu_erf(c[mt][nt][2] + bv0);
                    v1.y = gelu_erf(c[mt][nt][3] + bv1);
                    *(float2*)(hsm + (r0 + mt * 16) * HSTR + ncol) = v0;
                    *(float2*)(hsm + (r0 + mt * 16 + 8) * HSTR + ncol) = v1;
                }
            }
        }
        __syncthreads();

        // ---- GEMM2 partial over this chunk's 128 n ----
        #pragma unroll
        for (int p = 0; p < 2; ++p) {
            const int idx = tid + p * NTHREADS;
            if (idx < TM * odim) {
                const int m = idx / odim;
                const int o = idx - m * odim;
                const float* hrow = hsm + m * HSTR;
                const float* wrow = w2t + o * W2STR + nc * NCHUNK;
                float s2 = 0.f;
                #pragma unroll 8
                for (int n4 = 0; n4 < NCHUNK / 4; ++n4) {
                    const float4 hv = *(const float4*)(hrow + n4 * 4);
                    const float4 wv = *(const float4*)(wrow + n4 * 4);
                    s2 += hv.x * wv.x + hv.y * wv.y + hv.z * wv.z + hv.w * wv.w;
                }
                oacc[p] += s2;
            }
        }
    }

    // ---- final write ----
    #pragma unroll
    for (int p = 0; p < 2; ++p) {
        const int idx = tid + p * NTHREADS;
        if (idx < TM * odim) {
            const int m = idx / odim;
            const int o = idx - m * odim;
            const int token = tok0 + m;
            if (token < BT)
                out[(size_t)token * OUTC + colbase + o] = oacc[p] + b2[o];
        }
    }
}

extern "C" void kernel_launch(void* const* d_in, const int* in_sizes, int n_in,
                              void* d_out, int out_size)
{
    const float* x   = (const float*)d_in[0];
    const float* W1  = (const float*)d_in[1];
    const float* b1  = (const float*)d_in[2];
    const float* W2a = (const float*)d_in[3];
    const float* b2a = (const float*)d_in[4];
    const float* W2b = (const float*)d_in[5];
    const float* b2b = (const float*)d_in[6];
    float* out = (float*)d_out;

    // 1) preconvert W1 -> bf16 hi/lo scratch (exact grid: 43*512*512/4/512 = 5504)
    convert_w1_kernel<<<5504, 512>>>(W1);

    // 2) fused split-GEMM
    cudaFuncSetAttribute(motion_decoder_mma,
                         cudaFuncAttributeMaxDynamicSharedMemorySize, SMEM_BYTES);
    dim3 grid((BT + TM - 1) / TM, NJ);   // 25 x 43
    motion_decoder_mma<<<grid, NTHREADS, SMEM_BYTES>>>(x, b1, W2a, b2a, W2b, b2b, out);
}

// round 7
// speedup vs baseline: 3.8465x; 1.1530x over previous
#include <cuda_runtime.h>
#include <cuda_bf16.h>
#include <math.h>
#include <stdint.h>

// ---------------- problem constants ----------------
#define BT      3136
#define NJ      43
#define NJ6     13
#define DLAT    512
#define OUTC    168

// ---------------- tiling ----------------
#define TM       128      // tokens per CTA
#define NCHUNK   128      // N per chunk (4 chunks)
#define KCH      64       // K per chunk (8 chunks)
#define NTHREADS 512      // 16 warps: 4 (m) x 4 (n), warp tile m32 n32

// ---------------- smem layout (bytes) ----------------
// A: 2 stages x (hi 16K + lo 16K)   = 65536
// B: 2 stages x (hi 16K + lo 16K)   = 65536
// b1s: 512 fp32                     = 2048
// w2t: [6][516] fp32                = 12384
// red: [4][128][8] fp32             = 16384
#define A_HI(b)  ((b)*32768)
#define A_LO(b)  ((b)*32768 + 16384)
#define OFF_B    65536
#define B_HI(b)  (OFF_B + (b)*32768)
#define B_LO(b)  (OFF_B + (b)*32768 + 16384)
#define OFF_B1   131072
#define OFF_W2T  133120
#define W2STR    516
#define OFF_RED  145504
#define SMEM_BYTES 161888

#define ASWZ(x) ((x) ^ (((x) >> 3) & 0x70))   // 128B rows
#define BSWZ(x) ((x) ^ (((x) >> 4) & 0x70))   // 256B rows

// ---------------- device scratch: preconverted bf16 hi/lo ----------------
__device__ __nv_bfloat16 g_w1hi[(size_t)NJ * DLAT * DLAT];
__device__ __nv_bfloat16 g_w1lo[(size_t)NJ * DLAT * DLAT];
__device__ __nv_bfloat16 g_xhi[(size_t)BT * NJ * DLAT];
__device__ __nv_bfloat16 g_xlo[(size_t)BT * NJ * DLAT];

__device__ __forceinline__ uint32_t smem_u32(const void* p) {
    uint32_t a;
    asm("{ .reg .u64 t; cvta.to.shared.u64 t, %1; cvt.u32.u64 %0, t; }" : "=r"(a) : "l"(p));
    return a;
}

__device__ __forceinline__ float gelu_erf(float v) {
    return 0.5f * v * (1.0f + erff(v * 0.70710678118654752f));
}

// ---------------- bf16 split helpers ----------------
__device__ __forceinline__ uint32_t pk(__nv_bfloat16 a, __nv_bfloat16 b) {
    return (uint32_t)__bfloat16_as_ushort(a) | ((uint32_t)__bfloat16_as_ushort(b) << 16);
}
__device__ __forceinline__ void split4(float4 v, uint2* h, uint2* l) {
    __nv_bfloat16 bx = __float2bfloat16(v.x), by = __float2bfloat16(v.y);
    __nv_bfloat16 bz = __float2bfloat16(v.z), bw = __float2bfloat16(v.w);
    h->x = pk(bx, by); h->y = pk(bz, bw);
    __nv_bfloat16 lx = __float2bfloat16(v.x - __bfloat162float(bx));
    __nv_bfloat16 ly = __float2bfloat16(v.y - __bfloat162float(by));
    __nv_bfloat16 lz = __float2bfloat16(v.z - __bfloat162float(bz));
    __nv_bfloat16 lw = __float2bfloat16(v.w - __bfloat162float(bw));
    l->x = pk(lx, ly); l->y = pk(lz, lw);
}

// ---------------- cp.async ----------------
__device__ __forceinline__ void cpa16(uint32_t dst, const void* src, int ssz) {
    asm volatile("cp.async.cg.shared.global [%0], [%1], 16, %2;"
                 :: "r"(dst), "l"(src), "r"(ssz) : "memory");
}
#define CP_COMMIT() asm volatile("cp.async.commit_group;" ::: "memory")
#define CP_WAIT0()  asm volatile("cp.async.wait_group 0;" ::: "memory")

// ---------------- mma / ldmatrix ----------------
__device__ __forceinline__ void ldsm4(uint32_t* r, uint32_t addr) {
    asm volatile("ldmatrix.sync.aligned.m8n8.x4.shared.b16 {%0,%1,%2,%3}, [%4];"
                 : "=r"(r[0]), "=r"(r[1]), "=r"(r[2]), "=r"(r[3]) : "r"(addr));
}
__device__ __forceinline__ void ldsm4t(uint32_t* r, uint32_t addr) {
    asm volatile("ldmatrix.sync.aligned.m8n8.x4.trans.shared.b16 {%0,%1,%2,%3}, [%4];"
                 : "=r"(r[0]), "=r"(r[1]), "=r"(r[2]), "=r"(r[3]) : "r"(addr));
}
__device__ __forceinline__ void mma16816(float* c, const uint32_t* a, const uint32_t* b) {
    asm volatile("mma.sync.aligned.m16n8k16.row.col.f32.bf16.bf16.f32 "
                 "{%0,%1,%2,%3}, {%4,%5,%6,%7}, {%8,%9}, {%0,%1,%2,%3};"
                 : "+f"(c[0]), "+f"(c[1]), "+f"(c[2]), "+f"(c[3])
                 : "r"(a[0]), "r"(a[1]), "r"(a[2]), "r"(a[3]), "r"(b[0]), "r"(b[1]));
}

// ---------------- preconvert kernels ----------------
__global__ __launch_bounds__(512, 2)
void convert_w1_kernel(const float* __restrict__ W1) {
    const size_t idx = (size_t)blockIdx.x * 512 + threadIdx.x;   // float4 index
    const float4 v = ((const float4*)W1)[idx];
    uint2 h, l; split4(v, &h, &l);
    ((uint2*)g_w1hi)[idx] = h;
    ((uint2*)g_w1lo)[idx] = l;
}
__global__ __launch_bounds__(512, 2)
void convert_x_kernel(const float* __restrict__ x) {
    const size_t idx = (size_t)blockIdx.x * 512 + threadIdx.x;   // float4 index
    const float4 v = ((const float4*)x)[idx];
    uint2 h, l; split4(v, &h, &l);
    ((uint2*)g_xhi)[idx] = h;
    ((uint2*)g_xlo)[idx] = l;
}

// ---------------- prefetch (bf16 gmem -> swizzled smem) ----------------
__device__ __forceinline__ void prefetch_a(uint32_t smb, int buf, int j, int tok0,
                                           int kc, int tid) {
    #pragma unroll
    for (int r = 0; r < 2; ++r) {
        const int idx = tid + r * NTHREADS;     // 0..1023
        const int m = idx >> 3, k8 = idx & 7;
        const int token = tok0 + m;
        const size_t g = ((size_t)token * NJ + j) * DLAT + kc * KCH + k8 * 8;
        const int ssz = (token < BT) ? 16 : 0;
        const uint32_t o = ASWZ((uint32_t)(m * 128 + k8 * 16));
        cpa16(smb + A_HI(buf) + o, g_xhi + g, ssz);
        cpa16(smb + A_LO(buf) + o, g_xlo + g, ssz);
    }
}
__device__ __forceinline__ void prefetch_b(uint32_t smb, int buf, int j, int kc,
                                           int nc, int tid) {
    const size_t base = (size_t)j * DLAT * DLAT + (size_t)(kc * KCH) * DLAT + nc * NCHUNK;
    #pragma unroll
    for (int r = 0; r < 2; ++r) {
        const int idx = tid + r * NTHREADS;     // 0..1023
        const int k = idx >> 4, n16 = idx & 15;
        const size_t g = base + (size_t)k * DLAT + n16 * 8;
        const uint32_t o = BSWZ((uint32_t)(k * 256 + n16 * 16));
        cpa16(smb + B_HI(buf) + o, g_w1hi + g, 16);
        cpa16(smb + B_LO(buf) + o, g_w1lo + g, 16);
    }
}

// ---------------- main kernel ----------------
__global__ __launch_bounds__(NTHREADS, 1)
void motion_decoder_mma(const float* __restrict__ b1,
                        const float* __restrict__ W2a,
                        const float* __restrict__ b2a,
                        const float* __restrict__ W2b,
                        const float* __restrict__ b2b,
                        float* __restrict__ out)
{
    extern __shared__ char sm[];
    const uint32_t smb = smem_u32(sm);
    const int tid = threadIdx.x;
    const int wid = tid >> 5, lane = tid & 31;
    const int wm = wid >> 2;               // 0..3 -> m offset wm*32
    const int wn = wid & 3;                // 0..3 -> n offset wn*32
    const int j = blockIdx.y;
    const int tok0 = blockIdx.x * TM;

    const int odim = (j < NJ6) ? 6 : 3;
    const float* W2 = (j < NJ6) ? (W2a + (size_t)j * DLAT * 6)
                                : (W2b + (size_t)(j - NJ6) * DLAT * 3);
    const float* b2 = (j < NJ6) ? (b2a + j * 6) : (b2b + (j - NJ6) * 3);
    const int colbase = (j < NJ6) ? j * 6 : (NJ6 * 6 + (j - NJ6) * 3);

    // pipeline prologue: stage 0 in flight
    prefetch_a(smb, 0, j, tok0, 0, tid);
    prefetch_b(smb, 0, j, 0, 0, tid);
    CP_COMMIT();

    // preload b1 and W2 (transposed to [o][n], zero-padded rows for odim==3)
    float* b1s = (float*)(sm + OFF_B1);
    for (int i = tid; i < DLAT; i += NTHREADS) b1s[i] = b1[j * DLAT + i];
    float* w2t = (float*)(sm + OFF_W2T);
    for (int i = tid; i < 6 * DLAT; i += NTHREADS) {
        const int o = i / DLAT, n = i - o * DLAT;
        w2t[o * W2STR + n] = (o < odim) ? W2[n * odim + o] : 0.f;
    }

    const int l15 = lane & 15;
    const int lhi = lane >> 4;

    // GEMM2 accumulators: [mt][rowhalf][o]
    float oacc[2][2][6];
    #pragma unroll
    for (int a = 0; a < 2; ++a)
        #pragma unroll
        for (int b = 0; b < 2; ++b)
            #pragma unroll
            for (int o = 0; o < 6; ++o) oacc[a][b][o] = 0.f;

    #pragma unroll 1
    for (int nc = 0; nc < 4; ++nc) {
        float c[2][4][4];
        #pragma unroll
        for (int mt = 0; mt < 2; ++mt)
            #pragma unroll
            for (int nt = 0; nt < 4; ++nt)
                #pragma unroll
                for (int q = 0; q < 4; ++q) c[mt][nt][q] = 0.f;

        #pragma unroll 1
        for (int kc = 0; kc < 8; ++kc) {
            const int s = nc * 8 + kc;
            CP_WAIT0();                    // stage s resident (own group)
            __syncthreads();               // visible to all; prior readers done

            if (s < 31) {                  // prefetch s+1 during MMA(s)
                const int s2 = s + 1;
                prefetch_a(smb, s2 & 1, j, tok0, s2 & 7, tid);
                prefetch_b(smb, s2 & 1, j, s2 & 7, s2 >> 3, tid);
                CP_COMMIT();
            }

            const int buf = s & 1;
            const uint32_t abh = smb + A_HI(buf), abl = smb + A_LO(buf);
            const uint32_t bbh = smb + B_HI(buf), bbl = smb + B_LO(buf);

            #pragma unroll
            for (int kt = 0; kt < 4; ++kt) {
                uint32_t ah[2][4], bh[2][4], bl[2][4], al[4];
                #pragma unroll
                for (int mt = 0; mt < 2; ++mt) {
                    const int row = wm * 32 + mt * 16 + l15;
                    ldsm4(ah[mt], abh + ASWZ((uint32_t)(row * 128 + kt * 32 + lhi * 16)));
                }
                #pragma unroll
                for (int nt2 = 0; nt2 < 2; ++nt2) {
                    const int krow = kt * 16 + l15;
                    ldsm4t(bh[nt2], bbh + BSWZ((uint32_t)(krow * 256 + wn * 64 + nt2 * 32 + lhi * 16)));
                }
                #pragma unroll
                for (int mt = 0; mt < 2; ++mt)
                    #pragma unroll
                    for (int nt = 0; nt < 4; ++nt)
                        mma16816(c[mt][nt], ah[mt], &bh[nt >> 1][(nt & 1) * 2]);
                #pragma unroll
                for (int nt2 = 0; nt2 < 2; ++nt2) {
                    const int krow = kt * 16 + l15;
                    ldsm4t(bl[nt2], bbl + BSWZ((uint32_t)(krow * 256 + wn * 64 + nt2 * 32 + lhi * 16)));
                }
                #pragma unroll
                for (int mt = 0; mt < 2; ++mt)
                    #pragma unroll
                    for (int nt = 0; nt < 4; ++nt)
                        mma16816(c[mt][nt], ah[mt], &bl[nt >> 1][(nt & 1) * 2]);
                #pragma unroll
                for (int mt = 0; mt < 2; ++mt) {
                    const int row = wm * 32 + mt * 16 + l15;
                    ldsm4(al, abl + ASWZ((uint32_t)(row * 128 + kt * 32 + lhi * 16)));
                    #pragma unroll
                    for (int nt = 0; nt < 4; ++nt)
                        mma16816(c[mt][nt], al, &bh[nt >> 1][(nt & 1) * 2]);
                }
            }
        }

        // ---- fused epilogue: bias + GELU + GEMM2 partial, registers only ----
        #pragma unroll
        for (int nt = 0; nt < 4; ++nt) {
            const int ncol = wn * 32 + nt * 8 + (lane & 3) * 2;
            const int ng = nc * NCHUNK + ncol;
            const float bv0 = b1s[ng], bv1 = b1s[ng + 1];
            #pragma unroll
            for (int mt = 0; mt < 2; ++mt) {
                const float h0 = gelu_erf(c[mt][nt][0] + bv0);
                const float h1 = gelu_erf(c[mt][nt][1] + bv1);
                const float h2 = gelu_erf(c[mt][nt][2] + bv0);
                const float h3 = gelu_erf(c[mt][nt][3] + bv1);
                if (odim == 6) {
                    #pragma unroll
                    for (int o = 0; o < 6; ++o) {
                        const float w0 = w2t[o * W2STR + ng];
                        const float w1 = w2t[o * W2STR + ng + 1];
                        oacc[mt][0][o] += h0 * w0 + h1 * w1;
                        oacc[mt][1][o] += h2 * w0 + h3 * w1;
                    }
                } else {
                    #pragma unroll
                    for (int o = 0; o < 3; ++o) {
                        const float w0 = w2t[o * W2STR + ng];
                        const float w1 = w2t[o * W2STR + ng + 1];
                        oacc[mt][0][o] += h0 * w0 + h1 * w1;
                        oacc[mt][1][o] += h2 * w0 + h3 * w1;
                    }
                }
            }
        }
    }

    // ---- reduction: quad butterfly, then cross-warp via smem ----
    #pragma unroll
    for (int mt = 0; mt < 2; ++mt)
        #pragma unroll
        for (int i = 0; i < 2; ++i)
            #pragma unroll
            for (int o = 0; o < 6; ++o) {
                float v = oacc[mt][i][o];
                v += __shfl_xor_sync(0xffffffffu, v, 1);
                v += __shfl_xor_sync(0xffffffffu, v, 2);
                oacc[mt][i][o] = v;
            }

    float* red = (float*)(sm + OFF_RED);
    __syncthreads();                       // MMA/epilogue all done (smem reuse safety)
    if ((lane & 3) == 0) {
        const int g = lane >> 2;
        #pragma unroll
        for (int mt = 0; mt < 2; ++mt)
            #pragma unroll
            for (int i = 0; i < 2; ++i) {
                const int row = wm * 32 + mt * 16 + i * 8 + g;
                #pragma unroll
                for (int o = 0; o < 6; ++o)
                    red[(wn * 128 + row) * 8 + o] = oacc[mt][i][o];
            }
    }
    __syncthreads();

    #pragma unroll
    for (int p = 0; p < 2; ++p) {
        const int idx = tid + p * NTHREADS;
        if (idx < TM * odim) {
            const int m = idx / odim;
            const int o = idx - m * odim;
            const int token = tok0 + m;
            if (token < BT) {
                const float sdm = red[m * 8 + o] + red[(128 + m) * 8 + o]
                                + red[(256 + m) * 8 + o] + red[(384 + m) * 8 + o];
                out[(size_t)token * OUTC + colbase + o] = sdm + b2[o];
            }
        }
    }
}

extern "C" void kernel_launch(void* const* d_in, const int* in_sizes, int n_in,
                              void* d_out, int out_size)
{
    const float* x   = (const float*)d_in[0];
    const float* W1  = (const float*)d_in[1];
    const float* b1  = (const float*)d_in[2];
    const float* W2a = (const float*)d_in[3];
    const float* b2a = (const float*)d_in[4];
    const float* W2b = (const float*)d_in[5];
    const float* b2b = (const float*)d_in[6];
    float* out = (float*)d_out;

    // 1) preconvert to bf16 hi/lo (exact grids)
    convert_w1_kernel<<<5504, 512>>>(W1);       // 43*512*512/4/512
    convert_x_kernel<<<33712, 512>>>(x);        // 3136*43*512/4/512

    // 2) fused split-GEMM
    cudaFuncSetAttribute(motion_decoder_mma,
                         cudaFuncAttributeMaxDynamicSharedMemorySize, SMEM_BYTES);
    dim3 grid((BT + TM - 1) / TM, NJ);          // 25 x 43
    motion_decoder_mma<<<grid, NTHREADS, SMEM_BYTES>>>(b1, W2a, b2a, W2b, b2b, out);
}